// round 16
// baseline (speedup 1.0000x reference)
#include <cuda_runtime.h>
#include <cuda_fp16.h>
#include <math.h>
#include <stdint.h>

// ---------------------------------------------------------------------------
// Problem constants
// ---------------------------------------------------------------------------
#define BB 4
#define SS 4096
#define DD 1024
#define HH 16
#define DH 64
#define FF 64
#define DFF 4096
#define NTOK (BB * SS)            // 16384 tokens

// ---------------------------------------------------------------------------
// Scratch (static device globals)
// ---------------------------------------------------------------------------
__device__ float g_q[(size_t)NTOK * DD];       // fp16 q view
__device__ __half g_kbuf[(size_t)NTOK * DD];
__device__ __half g_vbuf[(size_t)NTOK * DD];
__device__ __half g_h[(size_t)NTOK * DD];      // LN out (A operand), fp16
__device__ __half g_at[(size_t)NTOK * DD];     // attn out (A of wo), fp16
__device__ __half g_ffn[(size_t)NTOK * DFF];   // gelu out (A of w2), fp16
// Transposed single-fp16 weights, [N, K]
__device__ __half g_wqkvT[3 * DD * DD];    // folded q, folded k, v
__device__ __half g_woT[DD * DD];
__device__ __half g_w1T[(size_t)DFF * DD];
__device__ __half g_w2T[(size_t)DD * DFF];
// linear-attention small tensors
__device__ float g_kvp[2 * 64 * FF * DH];  // kv partials (2 K-chunks)
__device__ __half g_kvT[64 * FF * DH];     // [bh][d][f] fp16 (B^T for attn mma)
__device__ float g_ksum[64 * FF];

// ---------------------------------------------------------------------------
// PTX helpers (baseline PTX only — no 'a'-suffix features)
// ---------------------------------------------------------------------------
__device__ __forceinline__ uint32_t smem_u32(const void* p) {
    uint32_t a;
    asm("{ .reg .u64 t; cvta.to.shared.u64 t, %1; cvt.u32.u64 %0, t; }"
        : "=r"(a) : "l"(p));
    return a;
}
__device__ __forceinline__ void cp_async16(uint32_t dst, const void* src) {
    asm volatile("cp.async.cg.shared.global [%0], [%1], 16;\n" :: "r"(dst), "l"(src));
}
__device__ __forceinline__ void cp_commit() {
    asm volatile("cp.async.commit_group;\n" ::: "memory");
}
template <int N>
__device__ __forceinline__ void cp_wait() {
    asm volatile("cp.async.wait_group %0;\n" :: "n"(N) : "memory");
}
__device__ __forceinline__ void ldsm4(uint32_t& r0, uint32_t& r1, uint32_t& r2,
                                      uint32_t& r3, uint32_t addr) {
    asm volatile("ldmatrix.sync.aligned.m8n8.x4.shared.b16 {%0,%1,%2,%3}, [%4];"
                 : "=r"(r0), "=r"(r1), "=r"(r2), "=r"(r3) : "r"(addr));
}
__device__ __forceinline__ void ldsm4t(uint32_t& r0, uint32_t& r1, uint32_t& r2,
                                       uint32_t& r3, uint32_t addr) {
    asm volatile("ldmatrix.sync.aligned.m8n8.x4.trans.shared.b16 {%0,%1,%2,%3}, [%4];"
                 : "=r"(r0), "=r"(r1), "=r"(r2), "=r"(r3) : "r"(addr));
}
__device__ __forceinline__ void mma16816(float* c, const uint32_t* a,
                                         uint32_t b0, uint32_t b1) {
    asm volatile(
        "mma.sync.aligned.m16n8k16.row.col.f32.f16.f16.f32 "
        "{%0,%1,%2,%3}, {%4,%5,%6,%7}, {%8,%9}, {%0,%1,%2,%3};"
        : "+f"(c[0]), "+f"(c[1]), "+f"(c[2]), "+f"(c[3])
        : "r"(a[0]), "r"(a[1]), "r"(a[2]), "r"(a[3]), "r"(b0), "r"(b1));
}

// swizzled 16B-chunk offset within an Rx64 fp16 tile (128B rows, 8-phase XOR)
__device__ __forceinline__ uint32_t tile_off(int row, int ch) {
    return (uint32_t)(row * 128 + ((ch ^ (row & 7)) << 4));
}

// ---------------------------------------------------------------------------
// Fold proj into a QK weight and write TRANSPOSED fp16 directly:
//   outT[(h*64+f)*DD + d] = fp16( sum_dh W[d, h*64+dh] * proj[dh, f] )
// ---------------------------------------------------------------------------
__global__ __launch_bounds__(256) void fold_kernel(const float* __restrict__ W,
                                                   const float* __restrict__ proj,
                                                   __half* __restrict__ outT)
{
    __shared__ float projS[64][64];
    __shared__ float wS[64][65];
    int d0 = blockIdx.x * 64, h = blockIdx.y;
    int tid = threadIdx.x;
    for (int i = tid; i < 64 * 64; i += 256)
        projS[i >> 6][i & 63] = proj[i];
    for (int i = tid; i < 64 * 64; i += 256)
        wS[i >> 6][i & 63] = W[(size_t)(d0 + (i >> 6)) * (HH * DH) + h * 64 + (i & 63)];
    __syncthreads();
    int r = tid >> 2;              // local d
    int fb = (tid & 3) * 16;       // f base
    float acc[16];
    #pragma unroll
    for (int i = 0; i < 16; i++) acc[i] = 0.f;
    #pragma unroll 8
    for (int c = 0; c < 64; c++) {
        float w = wS[r][c];
        #pragma unroll
        for (int i = 0; i < 16; i++)
            acc[i] = fmaf(w, projS[c][fb + i], acc[i]);
    }
    #pragma unroll
    for (int i = 0; i < 16; i++)
        outT[(size_t)(h * 64 + fb + i) * DD + d0 + r] = __float2half_rn(acc[i]);
}

// ---------------------------------------------------------------------------
// Weight transpose + fp16 convert:  W[K,N] -> Wt[N,K]
// ---------------------------------------------------------------------------
__global__ __launch_bounds__(256) void ts_kernel(const float* __restrict__ W,
                                                 __half* __restrict__ o,
                                                 int K, int N)
{
    __shared__ float t[32][33];
    int n0 = blockIdx.x * 32, k0 = blockIdx.y * 32;
    int tx = threadIdx.x & 31, ty = threadIdx.x >> 5;
    for (int r = ty; r < 32; r += 8)
        t[r][tx] = W[(size_t)(k0 + r) * N + n0 + tx];
    __syncthreads();
    for (int r = ty; r < 32; r += 8)
        o[(size_t)(n0 + r) * K + k0 + tx] = __float2half_rn(t[tx][r]);
}

// ---------------------------------------------------------------------------
// LayerNorm -> fp16. One block (256 thr) per row of 1024.
// ---------------------------------------------------------------------------
__global__ __launch_bounds__(256) void ln_kernel(const float* __restrict__ x,
                                                 const float* __restrict__ g,
                                                 const float* __restrict__ b,
                                                 __half* __restrict__ o)
{
    int row = blockIdx.x;
    int t = threadIdx.x;
    const float4* xr = reinterpret_cast<const float4*>(x + (size_t)row * DD);
    float4 xv = xr[t];

    float s  = xv.x + xv.y + xv.z + xv.w;
    float s2 = xv.x*xv.x + xv.y*xv.y + xv.z*xv.z + xv.w*xv.w;

    __shared__ float red[2][8];
    #pragma unroll
    for (int off = 16; off > 0; off >>= 1) {
        s  += __shfl_xor_sync(0xffffffffu, s,  off);
        s2 += __shfl_xor_sync(0xffffffffu, s2, off);
    }
    int w = t >> 5, l = t & 31;
    if (l == 0) { red[0][w] = s; red[1][w] = s2; }
    __syncthreads();
    __shared__ float smu, srstd;
    if (t == 0) {
        float ts = 0.f, ts2 = 0.f;
        #pragma unroll
        for (int i = 0; i < 8; i++) { ts += red[0][i]; ts2 += red[1][i]; }
        float mu = ts * (1.0f / DD);
        float var = ts2 * (1.0f / DD) - mu * mu;
        smu = mu;
        srstd = rsqrtf(var + 1e-5f);
    }
    __syncthreads();
    float mu = smu, rstd = srstd;

    const float4 gv = reinterpret_cast<const float4*>(g)[t];
    const float4 bv = reinterpret_cast<const float4*>(b)[t];
    float o0 = (xv.x - mu) * rstd * gv.x + bv.x;
    float o1 = (xv.y - mu) * rstd * gv.y + bv.y;
    float o2 = (xv.z - mu) * rstd * gv.z + bv.z;
    float o3 = (xv.w - mu) * rstd * gv.w + bv.w;
    size_t idx = (size_t)row * DD + t * 4;
    __half2 p0 = __halves2half2(__float2half_rn(o0), __float2half_rn(o1));
    __half2 p1 = __halves2half2(__float2half_rn(o2), __float2half_rn(o3));
    *reinterpret_cast<__half2*>(o + idx)     = p0;
    *reinterpret_cast<__half2*>(o + idx + 2) = p1;
}

// ---------------------------------------------------------------------------
// HMMA GEMM: 128x128 tile, BK=64, 3-stage cp.async pipeline, 256 threads,
// 2 CTAs/SM (96KB smem each), 2x4 warp grid, warp tile 64x32.
// mode 0: Cf = val
// mode 1: Cf = val + bias + residual
// mode 2: Ch = fp16(gelu(val + bias))
// mode 3: fused qkv (fp16 outs): seg0 relu+eps->Ch(q), seg1 relu+eps->kOut,
//         seg2 ->vOut  (out stride 1024)
// ---------------------------------------------------------------------------
#define STAGE_BYTES 32768
#define NSTAGE 3
#define GEMM_SMEM (NSTAGE * STAGE_BYTES)
#define GTHREADS 256

__device__ __forceinline__ void load_stage(
    uint32_t st, const char* A, const char* B,
    int K, int row0, int col0, int kc, int tid)
{
    size_t kb = (size_t)kc * 128;
    #pragma unroll
    for (int i = 0; i < 4; i++) {
        int id = tid + GTHREADS * i;
        int row = id >> 3, ch = id & 7;
        size_t ga = (size_t)(row0 + row) * K * 2 + kb + ch * 16;
        cp_async16(st + tile_off(row, ch), A + ga);
    }
    #pragma unroll
    for (int i = 0; i < 4; i++) {
        int id = tid + GTHREADS * i;
        int row = id >> 3, ch = id & 7;
        size_t gb = (size_t)(col0 + row) * K * 2 + kb + ch * 16;
        cp_async16(st + 16384 + tile_off(row, ch), B + gb);
    }
}

__global__ __launch_bounds__(GTHREADS, 2) void mma_gemm_kernel(
    const __half* __restrict__ A, const __half* __restrict__ B,
    int M, int N, int K,
    float* __restrict__ Cf, const float* __restrict__ bias,
    const float* __restrict__ residual,
    __half* __restrict__ Ch,
    __half* __restrict__ kOut, __half* __restrict__ vOut, int mode)
{
    extern __shared__ char smem[];
    uint32_t sbase = smem_u32(smem);

    int tid = threadIdx.x;
    int wid = tid >> 5, l = tid & 31;
    int wr = wid >> 2, wc = wid & 3;   // 2x4 warp grid: 64x32 per warp
    int row0 = blockIdx.y * 128;
    int col0 = blockIdx.x * 128;
    int CH = K >> 6;

    const char* pA = (const char*)A;
    const char* pB = (const char*)B;

    float acc[4][4][4];
    #pragma unroll
    for (int i = 0; i < 4; i++)
        #pragma unroll
        for (int j = 0; j < 4; j++)
            #pragma unroll
            for (int t = 0; t < 4; t++) acc[i][j][t] = 0.f;

    int aRow = wr * 64 + (l & 15);
    int aHalf = (l >> 4) & 1;
    int bRowL = (l & 7) + ((l >> 4) & 1) * 8;
    int bHalf = (l >> 3) & 1;

    load_stage(sbase,               pA, pB, K, row0, col0, 0, tid);
    cp_commit();
    load_stage(sbase + STAGE_BYTES, pA, pB, K, row0, col0, 1, tid);
    cp_commit();

    int sidx = 0;
    for (int c = 0; c < CH; c++) {
        cp_wait<1>();
        __syncthreads();
        int nc = c + 2 < CH ? c + 2 : CH - 1;
        int widx = sidx + 2; if (widx >= NSTAGE) widx -= NSTAGE;
        load_stage(sbase + widx * STAGE_BYTES, pA, pB, K, row0, col0, nc, tid);
        cp_commit();

        uint32_t st = sbase + sidx * STAGE_BYTES;
        #pragma unroll
        for (int ks = 0; ks < 4; ks++) {
            uint32_t af[4][4];
            #pragma unroll
            for (int mt = 0; mt < 4; mt++) {
                uint32_t off = tile_off(aRow + mt * 16, ks * 2 + aHalf);
                ldsm4(af[mt][0], af[mt][1], af[mt][2], af[mt][3], st + off);
            }
            uint32_t bf[4][2];
            #pragma unroll
            for (int p = 0; p < 2; p++) {
                uint32_t off = tile_off(wc * 32 + p * 16 + bRowL, ks * 2 + bHalf);
                ldsm4(bf[2*p][0], bf[2*p][1], bf[2*p+1][0], bf[2*p+1][1],
                      st + 16384 + off);
            }
            #pragma unroll
            for (int mt = 0; mt < 4; mt++)
                #pragma unroll
                for (int nt = 0; nt < 4; nt++)
                    mma16816(acc[mt][nt], af[mt], bf[nt][0], bf[nt][1]);
        }
        if (++sidx == NSTAGE) sidx = 0;
    }

    // epilogue
    int rb = row0 + wr * 64 + (l >> 2);
    int cb = col0 + wc * 32 + (l & 3) * 2;

    if (mode == 3) {
        int seg = col0 >> 10;
        __half* dst = (seg == 0) ? Ch : ((seg == 1) ? kOut : vOut);
        int csub = seg << 10;
        bool dorelu = (seg < 2);
        #pragma unroll
        for (int mt = 0; mt < 4; mt++)
            #pragma unroll
            for (int half = 0; half < 2; half++) {
                int r = rb + mt * 16 + half * 8;
                #pragma unroll
                for (int nt = 0; nt < 4; nt++) {
                    int ccol = cb + nt * 8 - csub;
                    float v0 = acc[mt][nt][half * 2];
                    float v1 = acc[mt][nt][half * 2 + 1];
                    if (dorelu) {
                        v0 = fmaxf(v0, 0.f) + 1e-6f;
                        v1 = fmaxf(v1, 0.f) + 1e-6f;
                    }
                    *reinterpret_cast<__half2*>(dst + (size_t)r * 1024 + ccol) =
                        __halves2half2(__float2half_rn(v0), __float2half_rn(v1));
                }
            }
        return;
    }

    #pragma unroll
    for (int mt = 0; mt < 4; mt++) {
        #pragma unroll
        for (int half = 0; half < 2; half++) {
            int r = rb + mt * 16 + half * 8;
            #pragma unroll
            for (int nt = 0; nt < 4; nt++) {
                int ccol = cb + nt * 8;
                float v0 = acc[mt][nt][half * 2];
                float v1 = acc[mt][nt][half * 2 + 1];
                if (mode == 2) {
                    v0 += bias[ccol];
                    v1 += bias[ccol + 1];
                    v0 = 0.5f * v0 * (1.0f + erff(v0 * 0.70710678118654752f));
                    v1 = 0.5f * v1 * (1.0f + erff(v1 * 0.70710678118654752f));
                    *reinterpret_cast<__half2*>(Ch + (size_t)r * N + ccol) =
                        __halves2half2(__float2half_rn(v0), __float2half_rn(v1));
                } else {
                    if (mode == 1) {
                        v0 += bias[ccol];
                        v1 += bias[ccol + 1];
                        const float2 rr = *reinterpret_cast<const float2*>(
                            residual + (size_t)r * N + ccol);
                        v0 += rr.x; v1 += rr.y;
                    }
                    float2 o; o.x = v0; o.y = v1;
                    *reinterpret_cast<float2*>(Cf + (size_t)r * N + ccol) = o;
                }
            }
        }
    }
}

// ---------------------------------------------------------------------------
// kv via tensor cores, K-split: grid (64 bh, 2 chunks of 2048 tokens).
// Writes fp32 partials kvp[chunk][bh][d][f].
// ---------------------------------------------------------------------------
#define KV_SMEM 65536
__global__ __launch_bounds__(128, 1) void kv_mma_kernel(
    const __half* __restrict__ kf, const __half* __restrict__ vv,
    float* __restrict__ kvp)
{
    extern __shared__ char smem[];
    uint32_t sb = smem_u32(smem);
    int bh = blockIdx.x;
    int chunk = blockIdx.y;
    int b = bh >> 4, h = bh & 15;
    int tid = threadIdx.x, w = tid >> 5, l = tid & 31;
    size_t gbase = (size_t)b * SS * DD + (size_t)h * 64
                 + (size_t)chunk * 2048 * DD;   // halfs

    float acc[4][8][4];
    #pragma unroll
    for (int i = 0; i < 4; i++)
        #pragma unroll
        for (int j = 0; j < 8; j++)
            #pragma unroll
            for (int t = 0; t < 4; t++) acc[i][j][t] = 0.f;

    int aTrow = ((l >> 4) & 1) * 8 + (l & 7);
    int aFoff = ((l >> 3) & 1) * 8;
    int bTrow = ((l >> 3) & 1) * 8 + (l & 7);
    int bDoff = ((l >> 4) & 1) * 8;

    auto load_tile = [&](int it) {
        uint32_t st = sb + (it & 1) * 16384;
        int t0 = it * 64;
        #pragma unroll
        for (int i = 0; i < 4; i++) {
            int id = tid + 128 * i;
            int row = id >> 3, ch = id & 7;
            size_t go = gbase + (size_t)(t0 + row) * DD + ch * 8;
            cp_async16(st + tile_off(row, ch),        (const char*)(kf + go));
            cp_async16(st + 8192 + tile_off(row, ch), (const char*)(vv + go));
        }
    };

    load_tile(0);
    cp_commit();

    for (int it = 0; it < 32; it++) {
        if (it < 31) { load_tile(it + 1); cp_commit(); cp_wait<1>(); }
        else cp_wait<0>();
        __syncthreads();
        uint32_t st = sb + (it & 1) * 16384;
        int t0w = w * 16;
        uint32_t af[4][4], bf[8][2];
        #pragma unroll
        for (int mt = 0; mt < 4; mt++) {
            int f0 = mt * 16 + aFoff;
            ldsm4t(af[mt][0], af[mt][1], af[mt][2], af[mt][3],
                   st + tile_off(t0w + aTrow, f0 >> 3));
        }
        #pragma unroll
        for (int p = 0; p < 4; p++) {
            int d0 = p * 16 + bDoff;
            uint32_t r0, r1, r2, r3;
            ldsm4t(r0, r1, r2, r3, st + 8192 + tile_off(t0w + bTrow, d0 >> 3));
            bf[2*p][0] = r0; bf[2*p][1] = r1;
            bf[2*p+1][0] = r2; bf[2*p+1][1] = r3;
        }
        #pragma unroll
        for (int mt = 0; mt < 4; mt++)
            #pragma unroll
            for (int nt = 0; nt < 8; nt++)
                mma16816(acc[mt][nt], af[mt], bf[nt][0], bf[nt][1]);
        __syncthreads();
    }

    // cross-warp reduce via smem: red[w][f][d]
    float* red = (float*)smem;
    #pragma unroll
    for (int mt = 0; mt < 4; mt++)
        #pragma unroll
        for (int half = 0; half < 2; half++) {
            int f = mt * 16 + half * 8 + (l >> 2);
            #pragma unroll
            for (int nt = 0; nt < 8; nt++) {
                int d = nt * 8 + (l & 3) * 2;
                red[w * 4096 + f * 64 + d]     = acc[mt][nt][half * 2];
                red[w * 4096 + f * 64 + d + 1] = acc[mt][nt][half * 2 + 1];
            }
        }
    __syncthreads();
    float* dst = kvp + (size_t)chunk * 64 * 4096 + (size_t)bh * 4096;
    for (int j = tid; j < 4096; j += 128) {
        int d = j >> 6, f = j & 63;
        int s = f * 64 + d;
        dst[j] = red[s] + red[4096 + s] + red[8192 + s] + red[12288 + s];
    }
}

// kvT[bh][j] = fp16(kvp[0][bh][j] + kvp[1][bh][j])
__global__ __launch_bounds__(256) void kv_reduce_kernel(const float* __restrict__ kvp,
                                                        __half* __restrict__ kvT)
{
    int i = blockIdx.x * 256 + threadIdx.x;
    kvT[i] = __float2half_rn(kvp[i] + kvp[64 * 4096 + i]);
}

// ---------------------------------------------------------------------------
// ksum[bh][f] = sum_t k[t][bh*64+f]   (grid 64, block 256: 4 token-slices)
// ---------------------------------------------------------------------------
__global__ __launch_bounds__(256) void ksum_kernel(const __half* __restrict__ kf,
                                                   float* __restrict__ ksum)
{
    __shared__ float part[4][64];
    int bh = blockIdx.x;
    int b = bh >> 4, h = bh & 15;
    int tid = threadIdx.x;
    int f = tid & 63, s = tid >> 6;
    size_t gbase = (size_t)b * SS * DD + (size_t)h * 64 + f;
    float acc = 0.f;
    for (int t = s * 1024; t < (s + 1) * 1024; t++)
        acc += __half2float(kf[gbase + (size_t)t * DD]);
    part[s][f] = acc;
    __syncthreads();
    if (tid < 64)
        ksum[bh * 64 + tid] = part[0][tid] + part[1][tid] + part[2][tid] + part[3][tid];
}

// ---------------------------------------------------------------------------
// attn via tensor cores: per (bh, 128-token tile):
//   num = q[128x64] @ kvT^T, den = q . ksum;  at = num/den (fp16)
// ---------------------------------------------------------------------------
__global__ __launch_bounds__(128) void attn_mma_kernel(
    const __half* __restrict__ qf, const __half* __restrict__ kvT,
    const float* __restrict__ ksum, __half* __restrict__ o)
{
    __shared__ __align__(16) char qs[128 * 128];
    __shared__ __align__(16) char kvs[64 * 128];
    __shared__ float sksum[64];
    __shared__ float sinv[128];

    int bh = blockIdx.x;
    int b = bh >> 4, h = bh & 15;
    int t0 = blockIdx.y * 128;
    int tid = threadIdx.x, w = tid >> 5, l = tid & 31;
    uint32_t qsb = smem_u32(qs), kvsb = smem_u32(kvs);
    size_t gbase = (size_t)b * SS * DD + (size_t)h * 64;

    #pragma unroll
    for (int i = 0; i < 8; i++) {
        int id = tid + 128 * i;
        int row = id >> 3, ch = id & 7;
        cp_async16(qsb + tile_off(row, ch),
                   (const char*)(qf + gbase + (size_t)(t0 + row) * DD + ch * 8));
    }
    #pragma unroll
    for (int i = 0; i < 4; i++) {
        int id = tid + 128 * i;
        int row = id >> 3, ch = id & 7;
        cp_async16(kvsb + tile_off(row, ch),
                   (const char*)(kvT + (size_t)bh * 4096 + row * 64 + ch * 8));
    }
    cp_commit();
    if (tid < 64) sksum[tid] = ksum[bh * 64 + tid];
    cp_wait<0>();
    __syncthreads();

    {
        float den = 0.f;
        #pragma unroll 8
        for (int f = 0; f < 64; f++) {
            __half qv = *reinterpret_cast<const __half*>(
                qs + tile_off(tid, f >> 3) + (f & 7) * 2);
            den = fmaf(__half2float(qv), sksum[f], den);
        }
        sinv[tid] = 1.0f / (den + 1e-6f);
    }
    __syncthreads();

    float acc[2][8][4];
    #pragma unroll
    for (int i = 0; i < 2; i++)
        #pragma unroll
        for (int j = 0; j < 8; j++)
            #pragma unroll
            for (int t = 0; t < 4; t++) acc[i][j][t] = 0.f;

    int aRow = w * 32 + (l & 15);
    int aHalf = (l >> 4) & 1;
    int bRowL = (l & 7) + ((l >> 4) & 1) * 8;
    int bHalf = (l >> 3) & 1;

    #pragma unroll
    for (int ks = 0; ks < 4; ks++) {
        uint32_t af[2][4], bf[8][2];
        #pragma unroll
        for (int mt = 0; mt < 2; mt++)
            ldsm4(af[mt][0], af[mt][1], af[mt][2], af[mt][3],
                  qsb + tile_off(aRow + mt * 16, ks * 2 + aHalf));
        #pragma unroll
        for (int p = 0; p < 4; p++)
            ldsm4(bf[2*p][0], bf[2*p][1], bf[2*p+1][0], bf[2*p+1][1],
                  kvsb + tile_off(p * 16 + bRowL, ks * 2 + bHalf));
        #pragma unroll
        for (int mt = 0; mt < 2; mt++)
            #pragma unroll
            for (int nt = 0; nt < 8; nt++)
                mma16816(acc[mt][nt], af[mt], bf[nt][0], bf[nt][1]);
    }

    #pragma unroll
    for (int mt = 0; mt < 2; mt++)
        #pragma unroll
        for (int half = 0; half < 2; half++) {
            int row = w * 32 + mt * 16 + half * 8 + (l >> 2);
            float inv = sinv[row];
            size_t obase = gbase + (size_t)(t0 + row) * DD;
            #pragma unroll
            for (int nt = 0; nt < 8; nt++) {
                int d = nt * 8 + (l & 3) * 2;
                float v0 = acc[mt][nt][half * 2] * inv;
                float v1 = acc[mt][nt][half * 2 + 1] * inv;
                *reinterpret_cast<__half2*>(o + obase + d) =
                    __halves2half2(__float2half_rn(v0), __float2half_rn(v1));
            }
        }
}

// ---------------------------------------------------------------------------
// Launch (fork-join dual-stream schedule; side stream hides weight prep,
// LN1, and ksum behind critical-path work)
// ---------------------------------------------------------------------------
extern "C" void kernel_launch(void* const* d_in, const int* in_sizes, int n_in,
                              void* d_out, int out_size)
{
    const float* x     = (const float*)d_in[0];
    const float* ln1_g = (const float*)d_in[1];
    const float* ln1_b = (const float*)d_in[2];
    const float* wq    = (const float*)d_in[3];
    const float* wk    = (const float*)d_in[4];
    const float* wv    = (const float*)d_in[5];
    const float* proj  = (const float*)d_in[6];
    const float* wo    = (const float*)d_in[7];
    const float* bo    = (const float*)d_in[8];
    const float* ln2_g = (const float*)d_in[9];
    const float* ln2_b = (const float*)d_in[10];
    const float* w1    = (const float*)d_in[11];
    const float* b1    = (const float*)d_in[12];
    const float* w2    = (const float*)d_in[13];
    const float* b2    = (const float*)d_in[14];
    float* out = (float*)d_out;

    float *qraw, *ksum, *kvp;
    __half *kbuf, *vbuf, *h, *at, *ffn, *wqkvT, *woT, *w1T, *w2T, *kvT;
    cudaGetSymbolAddress((void**)&qraw, g_q);
    cudaGetSymbolAddress((void**)&kbuf, g_kbuf);
    cudaGetSymbolAddress((void**)&vbuf, g_vbuf);
    cudaGetSymbolAddress((void**)&kvp, g_kvp);
    cudaGetSymbolAddress((void**)&kvT, g_kvT);
    cudaGetSymbolAddress((void**)&ksum, g_ksum);
    cudaGetSymbolAddress((void**)&h, g_h);
    cudaGetSymbolAddress((void**)&at, g_at);
    cudaGetSymbolAddress((void**)&ffn, g_ffn);
    cudaGetSymbolAddress((void**)&wqkvT, g_wqkvT);
    cudaGetSymbolAddress((void**)&woT, g_woT);
    cudaGetSymbolAddress((void**)&w1T, g_w1T);
    cudaGetSymbolAddress((void**)&w2T, g_w2T);
    __half* qbuf = (__half*)qraw;   // fp16 q view (front 32MB of 64MB buffer)

    cudaFuncSetAttribute(mma_gemm_kernel,
                         cudaFuncAttributeMaxDynamicSharedMemorySize, GEMM_SMEM);
    cudaFuncSetAttribute(kv_mma_kernel,
                         cudaFuncAttributeMaxDynamicSharedMemorySize, KV_SMEM);

    // host-side stream/event statics (no device memory; created once)
    static cudaStream_t sSide = nullptr;
    static cudaEvent_t evF = nullptr, evL = nullptr, evP = nullptr,
                       evQ = nullptr, evS = nullptr;
    if (!sSide) {
        cudaStreamCreateWithFlags(&sSide, cudaStreamNonBlocking);
        cudaEventCreateWithFlags(&evF, cudaEventDisableTiming);
        cudaEventCreateWithFlags(&evL, cudaEventDisableTiming);
        cudaEventCreateWithFlags(&evP, cudaEventDisableTiming);
        cudaEventCreateWithFlags(&evQ, cudaEventDisableTiming);
        cudaEventCreateWithFlags(&evS, cudaEventDisableTiming);
    }

    // ---- fork: side stream does LN1, then late-needed weight transposes ----
    cudaEventRecord(evF, 0);
    cudaStreamWaitEvent(sSide, evF, 0);
    ln_kernel<<<NTOK, 256, 0, sSide>>>(x, ln1_g, ln1_b, h);
    cudaEventRecord(evL, sSide);                // LN1 done (QKV dep)
    ts_kernel<<<dim3(DD / 32, DD / 32), 256, 0, sSide>>>(wo, woT, DD, DD);
    ts_kernel<<<dim3(DFF / 32, DD / 32), 256, 0, sSide>>>(w1, w1T, DD, DFF);
    ts_kernel<<<dim3(DD / 32, DFF / 32), 256, 0, sSide>>>(w2, w2T, DFF, DD);
    cudaEventRecord(evP, sSide);                // wo/w1/w2 transposes done

    // ---- main: QKV weight prep (critical path) ----
    fold_kernel<<<dim3(DD / 64, HH), 256>>>(wq, proj, wqkvT);
    fold_kernel<<<dim3(DD / 64, HH), 256>>>(wk, proj, wqkvT + 1024 * 1024);
    ts_kernel<<<dim3(DD / 32, DD / 32), 256>>>(wv, wqkvT + 2048 * 1024, DD, DD);

    // join LN1, run fused QKV GEMM
    cudaStreamWaitEvent(0, evL, 0);
    dim3 gQKV(3072 / 128, NTOK / 128);
    mma_gemm_kernel<<<gQKV, GTHREADS, GEMM_SMEM>>>(h, wqkvT,
        NTOK, 3072, DD, nullptr, nullptr, nullptr, qbuf, kbuf, vbuf, 3);

    // ---- fork: ksum on side (parallel with kv_mma/kv_reduce on main) ----
    cudaEventRecord(evQ, 0);
    cudaStreamWaitEvent(sSide, evQ, 0);
    ksum_kernel<<<64, 256, 0, sSide>>>(kbuf, ksum);
    cudaEventRecord(evS, sSide);

    kv_mma_kernel<<<dim3(64, 2), 128, KV_SMEM>>>(kbuf, vbuf, kvp);
    kv_reduce_kernel<<<64 * 4096 / 256, 256>>>(kvp, kvT);

    // join ksum, attn
    cudaStreamWaitEvent(0, evS, 0);
    attn_mma_kernel<<<dim3(64, SS / 128), 128>>>(qbuf, kvT, ksum, at);

    // join weight transposes, then the remaining GEMM chain
    cudaStreamWaitEvent(0, evP, 0);
    dim3 gD(DD / 128, NTOK / 128);
    mma_gemm_kernel<<<gD, GTHREADS, GEMM_SMEM>>>(at, woT,
        NTOK, DD, DD, out, bo, x, nullptr, nullptr, nullptr, 1);

    ln_kernel<<<NTOK, 256>>>(out, ln2_g, ln2_b, h);

    dim3 gF1(DFF / 128, NTOK / 128);
    mma_gemm_kernel<<<gF1, GTHREADS, GEMM_SMEM>>>(h, w1T,
        NTOK, DFF, DD, nullptr, b1, nullptr, ffn, nullptr, nullptr, 2);

    mma_gemm_kernel<<<gD, GTHREADS, GEMM_SMEM>>>(ffn, w2T,
        NTOK, DD, DFF, out, b2, out, nullptr, nullptr, nullptr, 1);
}

// round 17
// speedup vs baseline: 1.0398x; 1.0398x over previous
#include <cuda_runtime.h>
#include <cuda_fp16.h>
#include <math.h>
#include <stdint.h>

// ---------------------------------------------------------------------------
// Problem constants
// ---------------------------------------------------------------------------
#define BB 4
#define SS 4096
#define DD 1024
#define HH 16
#define DH 64
#define FF 64
#define DFF 4096
#define NTOK (BB * SS)            // 16384 tokens

// ---------------------------------------------------------------------------
// Scratch (static device globals)
// ---------------------------------------------------------------------------
__device__ float g_q[(size_t)NTOK * DD];       // fp16 q view
__device__ __half g_kbuf[(size_t)NTOK * DD];
__device__ __half g_vbuf[(size_t)NTOK * DD];
__device__ __half g_h[(size_t)NTOK * DD];      // LN out (A operand), fp16
__device__ __half g_at[(size_t)NTOK * DD];     // attn out (A of wo), fp16
__device__ __half g_ffn[(size_t)NTOK * DFF];   // gelu out (A of w2), fp16
// Transposed single-fp16 weights, [N, K]
__device__ __half g_wqkvT[3 * DD * DD];    // folded q, folded k, v
__device__ __half g_woT[DD * DD];
__device__ __half g_w1T[(size_t)DFF * DD];
__device__ __half g_w2T[(size_t)DD * DFF];
// linear-attention small tensors
__device__ float g_kvp[2 * 64 * FF * DH];  // kv partials (2 K-chunks)
__device__ __half g_kvT[64 * FF * DH];     // [bh][d][f] fp16 (B^T for attn mma)
__device__ float g_ksum[64 * FF];

// ---------------------------------------------------------------------------
// PTX helpers (baseline PTX only — no 'a'-suffix features)
// ---------------------------------------------------------------------------
__device__ __forceinline__ uint32_t smem_u32(const void* p) {
    uint32_t a;
    asm("{ .reg .u64 t; cvta.to.shared.u64 t, %1; cvt.u32.u64 %0, t; }"
        : "=r"(a) : "l"(p));
    return a;
}
__device__ __forceinline__ void cp_async16(uint32_t dst, const void* src) {
    asm volatile("cp.async.cg.shared.global [%0], [%1], 16;\n" :: "r"(dst), "l"(src));
}
__device__ __forceinline__ void cp_commit() {
    asm volatile("cp.async.commit_group;\n" ::: "memory");
}
template <int N>
__device__ __forceinline__ void cp_wait() {
    asm volatile("cp.async.wait_group %0;\n" :: "n"(N) : "memory");
}
__device__ __forceinline__ void ldsm4(uint32_t& r0, uint32_t& r1, uint32_t& r2,
                                      uint32_t& r3, uint32_t addr) {
    asm volatile("ldmatrix.sync.aligned.m8n8.x4.shared.b16 {%0,%1,%2,%3}, [%4];"
                 : "=r"(r0), "=r"(r1), "=r"(r2), "=r"(r3) : "r"(addr));
}
__device__ __forceinline__ void ldsm4t(uint32_t& r0, uint32_t& r1, uint32_t& r2,
                                       uint32_t& r3, uint32_t addr) {
    asm volatile("ldmatrix.sync.aligned.m8n8.x4.trans.shared.b16 {%0,%1,%2,%3}, [%4];"
                 : "=r"(r0), "=r"(r1), "=r"(r2), "=r"(r3) : "r"(addr));
}
__device__ __forceinline__ void mma16816(float* c, const uint32_t* a,
                                         uint32_t b0, uint32_t b1) {
    asm volatile(
        "mma.sync.aligned.m16n8k16.row.col.f32.f16.f16.f32 "
        "{%0,%1,%2,%3}, {%4,%5,%6,%7}, {%8,%9}, {%0,%1,%2,%3};"
        : "+f"(c[0]), "+f"(c[1]), "+f"(c[2]), "+f"(c[3])
        : "r"(a[0]), "r"(a[1]), "r"(a[2]), "r"(a[3]), "r"(b0), "r"(b1));
}

// swizzled 16B-chunk offset within an Rx64 fp16 tile (128B rows, 8-phase XOR)
__device__ __forceinline__ uint32_t tile_off(int row, int ch) {
    return (uint32_t)(row * 128 + ((ch ^ (row & 7)) << 4));
}

// ---------------------------------------------------------------------------
// Fold proj into a QK weight and write TRANSPOSED fp16 directly:
//   outT[(h*64+f)*DD + d] = fp16( sum_dh W[d, h*64+dh] * proj[dh, f] )
// ---------------------------------------------------------------------------
__global__ __launch_bounds__(256) void fold_kernel(const float* __restrict__ W,
                                                   const float* __restrict__ proj,
                                                   __half* __restrict__ outT)
{
    __shared__ float projS[64][64];
    __shared__ float wS[64][65];
    int d0 = blockIdx.x * 64, h = blockIdx.y;
    int tid = threadIdx.x;
    for (int i = tid; i < 64 * 64; i += 256)
        projS[i >> 6][i & 63] = proj[i];
    for (int i = tid; i < 64 * 64; i += 256)
        wS[i >> 6][i & 63] = W[(size_t)(d0 + (i >> 6)) * (HH * DH) + h * 64 + (i & 63)];
    __syncthreads();
    int r = tid >> 2;              // local d
    int fb = (tid & 3) * 16;       // f base
    float acc[16];
    #pragma unroll
    for (int i = 0; i < 16; i++) acc[i] = 0.f;
    #pragma unroll 8
    for (int c = 0; c < 64; c++) {
        float w = wS[r][c];
        #pragma unroll
        for (int i = 0; i < 16; i++)
            acc[i] = fmaf(w, projS[c][fb + i], acc[i]);
    }
    #pragma unroll
    for (int i = 0; i < 16; i++)
        outT[(size_t)(h * 64 + fb + i) * DD + d0 + r] = __float2half_rn(acc[i]);
}

// ---------------------------------------------------------------------------
// Weight transpose + fp16 convert:  W[K,N] -> Wt[N,K]
// Vectorized: 64(n) x 32(k) tile, float4 loads, half2 stores.
// grid (N/64, K/32), block 256.
// ---------------------------------------------------------------------------
__global__ __launch_bounds__(256) void ts_kernel(const float* __restrict__ W,
                                                 __half* __restrict__ o,
                                                 int K, int N)
{
    __shared__ float t[32][65];
    int n0 = blockIdx.x * 64, k0 = blockIdx.y * 32;
    int tid = threadIdx.x;
    // load 32 k-rows x 64 n floats (512 float4, 2 per thread)
    #pragma unroll
    for (int i = 0; i < 2; i++) {
        int id = tid + 256 * i;        // 0..511
        int kr = id >> 4;              // 0..31
        int nc = (id & 15) * 4;        // 0..60
        float4 v = *reinterpret_cast<const float4*>(
            W + (size_t)(k0 + kr) * N + n0 + nc);
        t[kr][nc] = v.x; t[kr][nc + 1] = v.y;
        t[kr][nc + 2] = v.z; t[kr][nc + 3] = v.w;
    }
    __syncthreads();
    // store 64 n-rows x 32 k halfs (8 halfs per thread)
    int n = tid >> 2;
    int kb = (tid & 3) * 8;
    __half* dst = o + (size_t)(n0 + n) * K + k0 + kb;
    #pragma unroll
    for (int j = 0; j < 8; j += 2) {
        __half2 p = __halves2half2(__float2half_rn(t[kb + j][n]),
                                   __float2half_rn(t[kb + j + 1][n]));
        *reinterpret_cast<__half2*>(dst + j) = p;
    }
}

// ---------------------------------------------------------------------------
// LayerNorm -> fp16. One block (256 thr) per row of 1024.
// ---------------------------------------------------------------------------
__global__ __launch_bounds__(256) void ln_kernel(const float* __restrict__ x,
                                                 const float* __restrict__ g,
                                                 const float* __restrict__ b,
                                                 __half* __restrict__ o)
{
    int row = blockIdx.x;
    int t = threadIdx.x;
    const float4* xr = reinterpret_cast<const float4*>(x + (size_t)row * DD);
    float4 xv = xr[t];

    float s  = xv.x + xv.y + xv.z + xv.w;
    float s2 = xv.x*xv.x + xv.y*xv.y + xv.z*xv.z + xv.w*xv.w;

    __shared__ float red[2][8];
    #pragma unroll
    for (int off = 16; off > 0; off >>= 1) {
        s  += __shfl_xor_sync(0xffffffffu, s,  off);
        s2 += __shfl_xor_sync(0xffffffffu, s2, off);
    }
    int w = t >> 5, l = t & 31;
    if (l == 0) { red[0][w] = s; red[1][w] = s2; }
    __syncthreads();
    __shared__ float smu, srstd;
    if (t == 0) {
        float ts = 0.f, ts2 = 0.f;
        #pragma unroll
        for (int i = 0; i < 8; i++) { ts += red[0][i]; ts2 += red[1][i]; }
        float mu = ts * (1.0f / DD);
        float var = ts2 * (1.0f / DD) - mu * mu;
        smu = mu;
        srstd = rsqrtf(var + 1e-5f);
    }
    __syncthreads();
    float mu = smu, rstd = srstd;

    const float4 gv = reinterpret_cast<const float4*>(g)[t];
    const float4 bv = reinterpret_cast<const float4*>(b)[t];
    float o0 = (xv.x - mu) * rstd * gv.x + bv.x;
    float o1 = (xv.y - mu) * rstd * gv.y + bv.y;
    float o2 = (xv.z - mu) * rstd * gv.z + bv.z;
    float o3 = (xv.w - mu) * rstd * gv.w + bv.w;
    size_t idx = (size_t)row * DD + t * 4;
    __half2 p0 = __halves2half2(__float2half_rn(o0), __float2half_rn(o1));
    __half2 p1 = __halves2half2(__float2half_rn(o2), __float2half_rn(o3));
    *reinterpret_cast<__half2*>(o + idx)     = p0;
    *reinterpret_cast<__half2*>(o + idx + 2) = p1;
}

// ---------------------------------------------------------------------------
// HMMA GEMM: 128x128 tile, BK=64, 3-stage cp.async pipeline, 256 threads,
// 2 CTAs/SM (96KB smem each), 2x4 warp grid, warp tile 64x32.
// mode 0: Cf = val
// mode 1: Cf = val + bias + residual
// mode 2: Ch = fp16(gelu(val + bias))
// mode 3: fused qkv (fp16 outs): seg0 relu+eps->Ch(q), seg1 relu+eps->kOut,
//         seg2 ->vOut  (out stride 1024)
// ---------------------------------------------------------------------------
#define STAGE_BYTES 32768
#define NSTAGE 3
#define GEMM_SMEM (NSTAGE * STAGE_BYTES)
#define GTHREADS 256

__device__ __forceinline__ void load_stage(
    uint32_t st, const char* A, const char* B,
    int K, int row0, int col0, int kc, int tid)
{
    size_t kb = (size_t)kc * 128;
    #pragma unroll
    for (int i = 0; i < 4; i++) {
        int id = tid + GTHREADS * i;
        int row = id >> 3, ch = id & 7;
        size_t ga = (size_t)(row0 + row) * K * 2 + kb + ch * 16;
        cp_async16(st + tile_off(row, ch), A + ga);
    }
    #pragma unroll
    for (int i = 0; i < 4; i++) {
        int id = tid + GTHREADS * i;
        int row = id >> 3, ch = id & 7;
        size_t gb = (size_t)(col0 + row) * K * 2 + kb + ch * 16;
        cp_async16(st + 16384 + tile_off(row, ch), B + gb);
    }
}

__global__ __launch_bounds__(GTHREADS, 2) void mma_gemm_kernel(
    const __half* __restrict__ A, const __half* __restrict__ B,
    int M, int N, int K,
    float* __restrict__ Cf, const float* __restrict__ bias,
    const float* __restrict__ residual,
    __half* __restrict__ Ch,
    __half* __restrict__ kOut, __half* __restrict__ vOut, int mode)
{
    extern __shared__ char smem[];
    uint32_t sbase = smem_u32(smem);

    int tid = threadIdx.x;
    int wid = tid >> 5, l = tid & 31;
    int wr = wid >> 2, wc = wid & 3;   // 2x4 warp grid: 64x32 per warp
    int row0 = blockIdx.y * 128;
    int col0 = blockIdx.x * 128;
    int CH = K >> 6;

    const char* pA = (const char*)A;
    const char* pB = (const char*)B;

    float acc[4][4][4];
    #pragma unroll
    for (int i = 0; i < 4; i++)
        #pragma unroll
        for (int j = 0; j < 4; j++)
            #pragma unroll
            for (int t = 0; t < 4; t++) acc[i][j][t] = 0.f;

    int aRow = wr * 64 + (l & 15);
    int aHalf = (l >> 4) & 1;
    int bRowL = (l & 7) + ((l >> 4) & 1) * 8;
    int bHalf = (l >> 3) & 1;

    load_stage(sbase,               pA, pB, K, row0, col0, 0, tid);
    cp_commit();
    load_stage(sbase + STAGE_BYTES, pA, pB, K, row0, col0, 1, tid);
    cp_commit();

    int sidx = 0;
    for (int c = 0; c < CH; c++) {
        cp_wait<1>();
        __syncthreads();
        int nc = c + 2 < CH ? c + 2 : CH - 1;
        int widx = sidx + 2; if (widx >= NSTAGE) widx -= NSTAGE;
        load_stage(sbase + widx * STAGE_BYTES, pA, pB, K, row0, col0, nc, tid);
        cp_commit();

        uint32_t st = sbase + sidx * STAGE_BYTES;
        #pragma unroll
        for (int ks = 0; ks < 4; ks++) {
            uint32_t af[4][4];
            #pragma unroll
            for (int mt = 0; mt < 4; mt++) {
                uint32_t off = tile_off(aRow + mt * 16, ks * 2 + aHalf);
                ldsm4(af[mt][0], af[mt][1], af[mt][2], af[mt][3], st + off);
            }
            uint32_t bf[4][2];
            #pragma unroll
            for (int p = 0; p < 2; p++) {
                uint32_t off = tile_off(wc * 32 + p * 16 + bRowL, ks * 2 + bHalf);
                ldsm4(bf[2*p][0], bf[2*p][1], bf[2*p+1][0], bf[2*p+1][1],
                      st + 16384 + off);
            }
            #pragma unroll
            for (int mt = 0; mt < 4; mt++)
                #pragma unroll
                for (int nt = 0; nt < 4; nt++)
                    mma16816(acc[mt][nt], af[mt], bf[nt][0], bf[nt][1]);
        }
        if (++sidx == NSTAGE) sidx = 0;
    }

    // epilogue
    int rb = row0 + wr * 64 + (l >> 2);
    int cb = col0 + wc * 32 + (l & 3) * 2;

    if (mode == 3) {
        int seg = col0 >> 10;
        __half* dst = (seg == 0) ? Ch : ((seg == 1) ? kOut : vOut);
        int csub = seg << 10;
        bool dorelu = (seg < 2);
        #pragma unroll
        for (int mt = 0; mt < 4; mt++)
            #pragma unroll
            for (int half = 0; half < 2; half++) {
                int r = rb + mt * 16 + half * 8;
                #pragma unroll
                for (int nt = 0; nt < 4; nt++) {
                    int ccol = cb + nt * 8 - csub;
                    float v0 = acc[mt][nt][half * 2];
                    float v1 = acc[mt][nt][half * 2 + 1];
                    if (dorelu) {
                        v0 = fmaxf(v0, 0.f) + 1e-6f;
                        v1 = fmaxf(v1, 0.f) + 1e-6f;
                    }
                    *reinterpret_cast<__half2*>(dst + (size_t)r * 1024 + ccol) =
                        __halves2half2(__float2half_rn(v0), __float2half_rn(v1));
                }
            }
        return;
    }

    #pragma unroll
    for (int mt = 0; mt < 4; mt++) {
        #pragma unroll
        for (int half = 0; half < 2; half++) {
            int r = rb + mt * 16 + half * 8;
            #pragma unroll
            for (int nt = 0; nt < 4; nt++) {
                int ccol = cb + nt * 8;
                float v0 = acc[mt][nt][half * 2];
                float v1 = acc[mt][nt][half * 2 + 1];
                if (mode == 2) {
                    v0 += bias[ccol];
                    v1 += bias[ccol + 1];
                    v0 = 0.5f * v0 * (1.0f + erff(v0 * 0.70710678118654752f));
                    v1 = 0.5f * v1 * (1.0f + erff(v1 * 0.70710678118654752f));
                    *reinterpret_cast<__half2*>(Ch + (size_t)r * N + ccol) =
                        __halves2half2(__float2half_rn(v0), __float2half_rn(v1));
                } else {
                    if (mode == 1) {
                        v0 += bias[ccol];
                        v1 += bias[ccol + 1];
                        const float2 rr = *reinterpret_cast<const float2*>(
                            residual + (size_t)r * N + ccol);
                        v0 += rr.x; v1 += rr.y;
                    }
                    float2 o; o.x = v0; o.y = v1;
                    *reinterpret_cast<float2*>(Cf + (size_t)r * N + ccol) = o;
                }
            }
        }
    }
}

// ---------------------------------------------------------------------------
// kv via tensor cores, K-split: grid (64 bh, 2 chunks of 2048 tokens).
// Writes fp32 partials kvp[chunk][bh][d][f].
// ---------------------------------------------------------------------------
#define KV_SMEM 65536
__global__ __launch_bounds__(128, 1) void kv_mma_kernel(
    const __half* __restrict__ kf, const __half* __restrict__ vv,
    float* __restrict__ kvp)
{
    extern __shared__ char smem[];
    uint32_t sb = smem_u32(smem);
    int bh = blockIdx.x;
    int chunk = blockIdx.y;
    int b = bh >> 4, h = bh & 15;
    int tid = threadIdx.x, w = tid >> 5, l = tid & 31;
    size_t gbase = (size_t)b * SS * DD + (size_t)h * 64
                 + (size_t)chunk * 2048 * DD;   // halfs

    float acc[4][8][4];
    #pragma unroll
    for (int i = 0; i < 4; i++)
        #pragma unroll
        for (int j = 0; j < 8; j++)
            #pragma unroll
            for (int t = 0; t < 4; t++) acc[i][j][t] = 0.f;

    int aTrow = ((l >> 4) & 1) * 8 + (l & 7);
    int aFoff = ((l >> 3) & 1) * 8;
    int bTrow = ((l >> 3) & 1) * 8 + (l & 7);
    int bDoff = ((l >> 4) & 1) * 8;

    auto load_tile = [&](int it) {
        uint32_t st = sb + (it & 1) * 16384;
        int t0 = it * 64;
        #pragma unroll
        for (int i = 0; i < 4; i++) {
            int id = tid + 128 * i;
            int row = id >> 3, ch = id & 7;
            size_t go = gbase + (size_t)(t0 + row) * DD + ch * 8;
            cp_async16(st + tile_off(row, ch),        (const char*)(kf + go));
            cp_async16(st + 8192 + tile_off(row, ch), (const char*)(vv + go));
        }
    };

    load_tile(0);
    cp_commit();

    for (int it = 0; it < 32; it++) {
        if (it < 31) { load_tile(it + 1); cp_commit(); cp_wait<1>(); }
        else cp_wait<0>();
        __syncthreads();
        uint32_t st = sb + (it & 1) * 16384;
        int t0w = w * 16;
        uint32_t af[4][4], bf[8][2];
        #pragma unroll
        for (int mt = 0; mt < 4; mt++) {
            int f0 = mt * 16 + aFoff;
            ldsm4t(af[mt][0], af[mt][1], af[mt][2], af[mt][3],
                   st + tile_off(t0w + aTrow, f0 >> 3));
        }
        #pragma unroll
        for (int p = 0; p < 4; p++) {
            int d0 = p * 16 + bDoff;
            uint32_t r0, r1, r2, r3;
            ldsm4t(r0, r1, r2, r3, st + 8192 + tile_off(t0w + bTrow, d0 >> 3));
            bf[2*p][0] = r0; bf[2*p][1] = r1;
            bf[2*p+1][0] = r2; bf[2*p+1][1] = r3;
        }
        #pragma unroll
        for (int mt = 0; mt < 4; mt++)
            #pragma unroll
            for (int nt = 0; nt < 8; nt++)
                mma16816(acc[mt][nt], af[mt], bf[nt][0], bf[nt][1]);
        __syncthreads();
    }

    // cross-warp reduce via smem: red[w][f][d]
    float* red = (float*)smem;
    #pragma unroll
    for (int mt = 0; mt < 4; mt++)
        #pragma unroll
        for (int half = 0; half < 2; half++) {
            int f = mt * 16 + half * 8 + (l >> 2);
            #pragma unroll
            for (int nt = 0; nt < 8; nt++) {
                int d = nt * 8 + (l & 3) * 2;
                red[w * 4096 + f * 64 + d]     = acc[mt][nt][half * 2];
                red[w * 4096 + f * 64 + d + 1] = acc[mt][nt][half * 2 + 1];
            }
        }
    __syncthreads();
    float* dst = kvp + (size_t)chunk * 64 * 4096 + (size_t)bh * 4096;
    for (int j = tid; j < 4096; j += 128) {
        int d = j >> 6, f = j & 63;
        int s = f * 64 + d;
        dst[j] = red[s] + red[4096 + s] + red[8192 + s] + red[12288 + s];
    }
}

// kvT[bh][j] = fp16(kvp[0][bh][j] + kvp[1][bh][j])
__global__ __launch_bounds__(256) void kv_reduce_kernel(const float* __restrict__ kvp,
                                                        __half* __restrict__ kvT)
{
    int i = blockIdx.x * 256 + threadIdx.x;
    kvT[i] = __float2half_rn(kvp[i] + kvp[64 * 4096 + i]);
}

// ---------------------------------------------------------------------------
// ksum[bh][f] = sum_t k[t][bh*64+f]   (grid 64, block 256: 4 token-slices)
// ---------------------------------------------------------------------------
__global__ __launch_bounds__(256) void ksum_kernel(const __half* __restrict__ kf,
                                                   float* __restrict__ ksum)
{
    __shared__ float part[4][64];
    int bh = blockIdx.x;
    int b = bh >> 4, h = bh & 15;
    int tid = threadIdx.x;
    int f = tid & 63, s = tid >> 6;
    size_t gbase = (size_t)b * SS * DD + (size_t)h * 64 + f;
    float acc = 0.f;
    for (int t = s * 1024; t < (s + 1) * 1024; t++)
        acc += __half2float(kf[gbase + (size_t)t * DD]);
    part[s][f] = acc;
    __syncthreads();
    if (tid < 64)
        ksum[bh * 64 + tid] = part[0][tid] + part[1][tid] + part[2][tid] + part[3][tid];
}

// ---------------------------------------------------------------------------
// attn via tensor cores: per (bh, 128-token tile):
//   num = q[128x64] @ kvT^T, den = q . ksum;  at = num/den (fp16)
// ---------------------------------------------------------------------------
__global__ __launch_bounds__(128) void attn_mma_kernel(
    const __half* __restrict__ qf, const __half* __restrict__ kvT,
    const float* __restrict__ ksum, __half* __restrict__ o)
{
    __shared__ __align__(16) char qs[128 * 128];
    __shared__ __align__(16) char kvs[64 * 128];
    __shared__ float sksum[64];
    __shared__ float sinv[128];

    int bh = blockIdx.x;
    int b = bh >> 4, h = bh & 15;
    int t0 = blockIdx.y * 128;
    int tid = threadIdx.x, w = tid >> 5, l = tid & 31;
    uint32_t qsb = smem_u32(qs), kvsb = smem_u32(kvs);
    size_t gbase = (size_t)b * SS * DD + (size_t)h * 64;

    #pragma unroll
    for (int i = 0; i < 8; i++) {
        int id = tid + 128 * i;
        int row = id >> 3, ch = id & 7;
        cp_async16(qsb + tile_off(row, ch),
                   (const char*)(qf + gbase + (size_t)(t0 + row) * DD + ch * 8));
    }
    #pragma unroll
    for (int i = 0; i < 4; i++) {
        int id = tid + 128 * i;
        int row = id >> 3, ch = id & 7;
        cp_async16(kvsb + tile_off(row, ch),
                   (const char*)(kvT + (size_t)bh * 4096 + row * 64 + ch * 8));
    }
    cp_commit();
    if (tid < 64) sksum[tid] = ksum[bh * 64 + tid];
    cp_wait<0>();
    __syncthreads();

    {
        float den = 0.f;
        #pragma unroll 8
        for (int f = 0; f < 64; f++) {
            __half qv = *reinterpret_cast<const __half*>(
                qs + tile_off(tid, f >> 3) + (f & 7) * 2);
            den = fmaf(__half2float(qv), sksum[f], den);
        }
        sinv[tid] = 1.0f / (den + 1e-6f);
    }
    __syncthreads();

    float acc[2][8][4];
    #pragma unroll
    for (int i = 0; i < 2; i++)
        #pragma unroll
        for (int j = 0; j < 8; j++)
            #pragma unroll
            for (int t = 0; t < 4; t++) acc[i][j][t] = 0.f;

    int aRow = w * 32 + (l & 15);
    int aHalf = (l >> 4) & 1;
    int bRowL = (l & 7) + ((l >> 4) & 1) * 8;
    int bHalf = (l >> 3) & 1;

    #pragma unroll
    for (int ks = 0; ks < 4; ks++) {
        uint32_t af[2][4], bf[8][2];
        #pragma unroll
        for (int mt = 0; mt < 2; mt++)
            ldsm4(af[mt][0], af[mt][1], af[mt][2], af[mt][3],
                  qsb + tile_off(aRow + mt * 16, ks * 2 + aHalf));
        #pragma unroll
        for (int p = 0; p < 4; p++)
            ldsm4(bf[2*p][0], bf[2*p][1], bf[2*p+1][0], bf[2*p+1][1],
                  kvsb + tile_off(p * 16 + bRowL, ks * 2 + bHalf));
        #pragma unroll
        for (int mt = 0; mt < 2; mt++)
            #pragma unroll
            for (int nt = 0; nt < 8; nt++)
                mma16816(acc[mt][nt], af[mt], bf[nt][0], bf[nt][1]);
    }

    #pragma unroll
    for (int mt = 0; mt < 2; mt++)
        #pragma unroll
        for (int half = 0; half < 2; half++) {
            int row = w * 32 + mt * 16 + half * 8 + (l >> 2);
            float inv = sinv[row];
            size_t obase = gbase + (size_t)(t0 + row) * DD;
            #pragma unroll
            for (int nt = 0; nt < 8; nt++) {
                int d = nt * 8 + (l & 3) * 2;
                float v0 = acc[mt][nt][half * 2] * inv;
                float v1 = acc[mt][nt][half * 2 + 1] * inv;
                *reinterpret_cast<__half2*>(o + obase + d) =
                    __halves2half2(__float2half_rn(v0), __float2half_rn(v1));
            }
        }
}

// ---------------------------------------------------------------------------
// Launch (single stream — R15 schedule; concurrency measurably hurts here)
// ---------------------------------------------------------------------------
extern "C" void kernel_launch(void* const* d_in, const int* in_sizes, int n_in,
                              void* d_out, int out_size)
{
    const float* x     = (const float*)d_in[0];
    const float* ln1_g = (const float*)d_in[1];
    const float* ln1_b = (const float*)d_in[2];
    const float* wq    = (const float*)d_in[3];
    const float* wk    = (const float*)d_in[4];
    const float* wv    = (const float*)d_in[5];
    const float* proj  = (const float*)d_in[6];
    const float* wo    = (const float*)d_in[7];
    const float* bo    = (const float*)d_in[8];
    const float* ln2_g = (const float*)d_in[9];
    const float* ln2_b = (const float*)d_in[10];
    const float* w1    = (const float*)d_in[11];
    const float* b1    = (const float*)d_in[12];
    const float* w2    = (const float*)d_in[13];
    const float* b2    = (const float*)d_in[14];
    float* out = (float*)d_out;

    float *qraw, *ksum, *kvp;
    __half *kbuf, *vbuf, *h, *at, *ffn, *wqkvT, *woT, *w1T, *w2T, *kvT;
    cudaGetSymbolAddress((void**)&qraw, g_q);
    cudaGetSymbolAddress((void**)&kbuf, g_kbuf);
    cudaGetSymbolAddress((void**)&vbuf, g_vbuf);
    cudaGetSymbolAddress((void**)&kvp, g_kvp);
    cudaGetSymbolAddress((void**)&kvT, g_kvT);
    cudaGetSymbolAddress((void**)&ksum, g_ksum);
    cudaGetSymbolAddress((void**)&h, g_h);
    cudaGetSymbolAddress((void**)&at, g_at);
    cudaGetSymbolAddress((void**)&ffn, g_ffn);
    cudaGetSymbolAddress((void**)&wqkvT, g_wqkvT);
    cudaGetSymbolAddress((void**)&woT, g_woT);
    cudaGetSymbolAddress((void**)&w1T, g_w1T);
    cudaGetSymbolAddress((void**)&w2T, g_w2T);
    __half* qbuf = (__half*)qraw;   // fp16 q view (front 32MB of 64MB buffer)

    cudaFuncSetAttribute(mma_gemm_kernel,
                         cudaFuncAttributeMaxDynamicSharedMemorySize, GEMM_SMEM);
    cudaFuncSetAttribute(kv_mma_kernel,
                         cudaFuncAttributeMaxDynamicSharedMemorySize, KV_SMEM);

    // --- weight prep (fold writes transposed fp16 directly) ---
    fold_kernel<<<dim3(DD / 64, HH), 256>>>(wq, proj, wqkvT);
    fold_kernel<<<dim3(DD / 64, HH), 256>>>(wk, proj, wqkvT + 1024 * 1024);
    ts_kernel<<<dim3(DD / 64, DD / 32), 256>>>(wv, wqkvT + 2048 * 1024, DD, DD);
    ts_kernel<<<dim3(DD / 64, DD / 32), 256>>>(wo, woT, DD, DD);
    ts_kernel<<<dim3(DFF / 64, DD / 32), 256>>>(w1, w1T, DD, DFF);
    ts_kernel<<<dim3(DD / 64, DFF / 32), 256>>>(w2, w2T, DFF, DD);

    // LN1 -> h (fp16)
    ln_kernel<<<NTOK, 256>>>(x, ln1_g, ln1_b, h);

    // Fused QKV GEMM: N=3072 -> q (relu+eps), k (relu+eps), v  (all fp16)
    dim3 gQKV(3072 / 128, NTOK / 128);
    mma_gemm_kernel<<<gQKV, GTHREADS, GEMM_SMEM>>>(h, wqkvT,
        NTOK, 3072, DD, nullptr, nullptr, nullptr, qbuf, kbuf, vbuf, 3);

    // kv (tensor cores, K-split) + reduce + ksum
    kv_mma_kernel<<<dim3(64, 2), 128, KV_SMEM>>>(kbuf, vbuf, kvp);
    ksum_kernel<<<64, 256>>>(kbuf, ksum);
    kv_reduce_kernel<<<64 * 4096 / 256, 256>>>(kvp, kvT);

    // attn (tensor cores) -> fp16
    attn_mma_kernel<<<dim3(64, SS / 128), 128>>>(qbuf, kvT, ksum, at);

    // x2 = x + attn @ wo + bo -> out (fp32)
    dim3 gD(DD / 128, NTOK / 128);
    mma_gemm_kernel<<<gD, GTHREADS, GEMM_SMEM>>>(at, woT,
        NTOK, DD, DD, out, bo, x, nullptr, nullptr, nullptr, 1);

    // LN2 -> h (fp16)
    ln_kernel<<<NTOK, 256>>>(out, ln2_g, ln2_b, h);

    // ffn = gelu(h2 @ w1 + b1) -> fp16
    dim3 gF1(DFF / 128, NTOK / 128);
    mma_gemm_kernel<<<gF1, GTHREADS, GEMM_SMEM>>>(h, w1T,
        NTOK, DFF, DD, nullptr, b1, nullptr, ffn, nullptr, nullptr, 2);

    // out = x2 + ffn @ w2 + b2 (in-place residual)
    mma_gemm_kernel<<<gD, GTHREADS, GEMM_SMEM>>>(ffn, w2T,
        NTOK, DD, DFF, out, b2, out, nullptr, nullptr, nullptr, 1);
}